// round 1
// baseline (speedup 1.0000x reference)
#include <cuda_runtime.h>
#include <math.h>

#define B_  32
#define L_  512
#define D_  32
#define K_  6
#define O_  192
#define DM_ 512

// ---------------- scratch (device globals; no allocation allowed) ----------------
__device__ float g_med_true[B_*D_];
__device__ float g_std_true[B_*D_];
__device__ float g_med_map[B_*D_*K_];
__device__ float g_std_map[B_*D_*K_];
__device__ float g_err[B_*D_*L_];      // (bd, l)  = x - mean_k(x_date_map)
__device__ float g_ymean[B_*D_*O_];    // (bd, o)  = mean_k(y_date_map)
__device__ float g_V[B_*D_*O_];        // attention output V (b,d,o)
__device__ float g_h[B_*D_*DM_];       // gelu(MLP hidden)
__device__ float g_w[B_*D_*2];         // softmax gate
__device__ float g_mu[D_];
__device__ float g_rstd[D_];

// ---------------- kernel 1: robust stats via smem bitonic sort ----------------
// grid: B*D blocks for x, then B*D*K blocks for x_date. 256 threads, 512 elems.
__global__ void stats_kernel(const float* __restrict__ x,
                             const float* __restrict__ x_date) {
    __shared__ float s[512];
    const int bid = blockIdx.x, tid = threadIdx.x;
    const float* base;
    int stride;
    if (bid < B_*D_) {
        int b = bid / D_, d = bid % D_;
        base = x + (size_t)b*L_*D_ + d;
        stride = D_;
    } else {
        int j  = bid - B_*D_;
        int bd = j / K_, k = j % K_;
        int b  = bd / D_, d = bd % D_;
        base = x_date + ((size_t)b*L_*D_ + d)*(size_t)K_ + k;
        stride = D_*K_;
    }
    s[tid]       = base[(size_t)tid * stride];
    s[tid + 256] = base[(size_t)(tid + 256) * stride];

    // bitonic sort, ascending, 512 elements / 256 comparators
    for (int size = 2; size < 512; size <<= 1) {
        const bool descBlock = (tid & (size >> 1)) != 0;
        for (int str = size >> 1; str > 0; str >>= 1) {
            __syncthreads();
            int pos = 2*tid - (tid & (str - 1));
            float a = s[pos], c = s[pos + str];
            bool sw = descBlock ? (a < c) : (a > c);
            if (sw) { s[pos] = c; s[pos + str] = a; }
        }
    }
    for (int str = 256; str > 0; str >>= 1) {
        __syncthreads();
        int pos = 2*tid - (tid & (str - 1));
        float a = s[pos], c = s[pos + str];
        if (a > c) { s[pos] = c; s[pos + str] = a; }
    }
    __syncthreads();

    if (tid == 0) {
        // torch.median (lower mid) = s[255]; quantile linear interp:
        // q=0.75: pos 383.25 ; q=0.25: pos 127.75
        float med = s[255];
        float q75 = s[383] + 0.25f * (s[384] - s[383]);
        float q25 = s[127] + 0.75f * (s[128] - s[127]);
        float sd  = q75 - q25 + 1e-6f;
        if (bid < B_*D_) { g_med_true[bid] = med; g_std_true[bid] = sd; }
        else { int j = bid - B_*D_; g_med_map[j] = med; g_std_map[j] = sd; }
    }
}

// ---------------- kernel 2: fused map + attention + err/ymean ----------------
// one block per (b,d); 256 threads = 8 warps; each warp owns 24 o-columns,
// processed in groups of 4 with scores kept in registers (one-pass softmax).
__global__ void __launch_bounds__(256) attn_kernel(const float* __restrict__ x,
                                                   const float* __restrict__ x_date,
                                                   const float* __restrict__ y_date) {
    __shared__ float sxd[K_][L_];     // mapped x_date, [k][l]
    __shared__ float syd[O_][K_];     // mapped y_date, [o][k]
    __shared__ float sx[L_];          // x column
    __shared__ float ssc[K_], ssh[K_];

    const int bd = blockIdx.x, tid = threadIdx.x;
    const int b = bd / D_, d = bd % D_;

    if (tid < K_) {
        float st = g_std_true[bd], mt = g_med_true[bd];
        float smv = g_std_map[bd*K_ + tid], mm = g_med_map[bd*K_ + tid];
        float sc = st / smv;
        ssc[tid] = sc;
        ssh[tid] = mt - mm * sc;
    }
    for (int l = tid; l < L_; l += 256)
        sx[l] = x[((size_t)b*L_ + l)*D_ + d];
    __syncthreads();

    for (int i = tid; i < L_*K_; i += 256) {
        int l = i / K_, k = i - l*K_;
        float v = x_date[(((size_t)b*L_ + l)*D_ + d)*(size_t)K_ + k];
        sxd[k][l] = fmaf(v, ssc[k], ssh[k]);
    }
    for (int i = tid; i < O_*K_; i += 256) {
        int o = i / K_, k = i - o*K_;
        float v = y_date[(((size_t)b*O_ + o)*D_ + d)*(size_t)K_ + k];
        syd[o][k] = fmaf(v, ssc[k], ssh[k]);
    }
    __syncthreads();

    // err = x - mean_k(x_date_map) ; ymean = mean_k(y_date_map)
    for (int l = tid; l < L_; l += 256) {
        float m = (sxd[0][l]+sxd[1][l]+sxd[2][l]+sxd[3][l]+sxd[4][l]+sxd[5][l]) * (1.0f/6.0f);
        g_err[(size_t)bd*L_ + l] = sx[l] - m;
    }
    for (int o = tid; o < O_; o += 256) {
        g_ymean[(size_t)bd*O_ + o] =
            (syd[o][0]+syd[o][1]+syd[o][2]+syd[o][3]+syd[o][4]+syd[o][5]) * (1.0f/6.0f);
    }

    const int warp = tid >> 5, lane = tid & 31;
    const float RS6 = 0.408248290463863f;   // 1/sqrt(6)

    for (int og = 0; og < 24; og += 4) {
        const int o0 = warp*24 + og;
        float yr[4][K_];
        #pragma unroll
        for (int j = 0; j < 4; j++)
            #pragma unroll
            for (int k = 0; k < K_; k++) yr[j][k] = syd[o0 + j][k];

        float sc[4][16];
        float mx[4] = {-3e38f, -3e38f, -3e38f, -3e38f};
        #pragma unroll
        for (int r = 0; r < 16; r++) {
            const int l = lane + (r << 5);
            float x0 = sxd[0][l], x1 = sxd[1][l], x2 = sxd[2][l];
            float x3 = sxd[3][l], x4 = sxd[4][l], x5 = sxd[5][l];
            #pragma unroll
            for (int j = 0; j < 4; j++) {
                float v = x0 * yr[j][0];
                v = fmaf(x1, yr[j][1], v);
                v = fmaf(x2, yr[j][2], v);
                v = fmaf(x3, yr[j][3], v);
                v = fmaf(x4, yr[j][4], v);
                v = fmaf(x5, yr[j][5], v);
                v *= RS6;
                sc[j][r] = v;
                mx[j] = fmaxf(mx[j], v);
            }
        }
        #pragma unroll
        for (int j = 0; j < 4; j++)
            #pragma unroll
            for (int off = 16; off; off >>= 1)
                mx[j] = fmaxf(mx[j], __shfl_xor_sync(0xffffffffu, mx[j], off));

        float sm[4] = {0,0,0,0}, vs[4] = {0,0,0,0};
        #pragma unroll
        for (int r = 0; r < 16; r++) {
            const float xl = sx[lane + (r << 5)];
            #pragma unroll
            for (int j = 0; j < 4; j++) {
                float p = __expf(sc[j][r] - mx[j]);
                sm[j] += p;
                vs[j] = fmaf(p, xl, vs[j]);
            }
        }
        #pragma unroll
        for (int j = 0; j < 4; j++)
            #pragma unroll
            for (int off = 16; off; off >>= 1) {
                sm[j] += __shfl_xor_sync(0xffffffffu, sm[j], off);
                vs[j] += __shfl_xor_sync(0xffffffffu, vs[j], off);
            }
        if (lane == 0) {
            #pragma unroll
            for (int j = 0; j < 4; j++)
                g_V[(size_t)bd*O_ + o0 + j] = vs[j] / sm[j];
        }
    }
}

// ---------------- kernel 3: tiled GEMM  H = gelu(E @ W1 + b1) ----------------
// C is (B*D=1024) x (DM=512). 64x64 tiles, BK=16, 256 threads, 4x4 micro-tile.
__global__ void __launch_bounds__(256) mlp1_kernel(const float* __restrict__ w1,
                                                   const float* __restrict__ b1) {
    __shared__ float Es[64][17];                 // [row][k], padded
    __shared__ __align__(16) float Ws[16][64];   // [k][col]
    const int tx = threadIdx.x & 15, ty = threadIdx.x >> 4;
    const int row0 = blockIdx.y * 64, col0 = blockIdx.x * 64;
    float acc[4][4] = {};

    for (int k0 = 0; k0 < 512; k0 += 16) {
        __syncthreads();
        #pragma unroll
        for (int it = 0; it < 4; it++) {
            int idx = threadIdx.x + it*256;
            int r  = idx >> 4, kk = idx & 15;
            Es[r][kk] = g_err[(size_t)(row0 + r)*512 + k0 + kk];
            int kw = idx >> 6, c = idx & 63;
            Ws[kw][c] = w1[(size_t)(k0 + kw)*512 + col0 + c];
        }
        __syncthreads();
        #pragma unroll
        for (int kk = 0; kk < 16; kk++) {
            float a0 = Es[ty*4+0][kk], a1 = Es[ty*4+1][kk];
            float a2 = Es[ty*4+2][kk], a3 = Es[ty*4+3][kk];
            const float4 bq = *reinterpret_cast<const float4*>(&Ws[kk][tx*4]);
            acc[0][0]=fmaf(a0,bq.x,acc[0][0]); acc[0][1]=fmaf(a0,bq.y,acc[0][1]);
            acc[0][2]=fmaf(a0,bq.z,acc[0][2]); acc[0][3]=fmaf(a0,bq.w,acc[0][3]);
            acc[1][0]=fmaf(a1,bq.x,acc[1][0]); acc[1][1]=fmaf(a1,bq.y,acc[1][1]);
            acc[1][2]=fmaf(a1,bq.z,acc[1][2]); acc[1][3]=fmaf(a1,bq.w,acc[1][3]);
            acc[2][0]=fmaf(a2,bq.x,acc[2][0]); acc[2][1]=fmaf(a2,bq.y,acc[2][1]);
            acc[2][2]=fmaf(a2,bq.z,acc[2][2]); acc[2][3]=fmaf(a2,bq.w,acc[2][3]);
            acc[3][0]=fmaf(a3,bq.x,acc[3][0]); acc[3][1]=fmaf(a3,bq.y,acc[3][1]);
            acc[3][2]=fmaf(a3,bq.z,acc[3][2]); acc[3][3]=fmaf(a3,bq.w,acc[3][3]);
        }
    }
    #pragma unroll
    for (int i = 0; i < 4; i++) {
        const int row = row0 + ty*4 + i;
        #pragma unroll
        for (int j = 0; j < 4; j++) {
            const int col = col0 + tx*4 + j;
            float v = acc[i][j] + b1[col];
            // exact gelu: 0.5*x*(1+erf(x/sqrt(2)))
            float g = 0.5f * v * (1.0f + erff(v * 0.7071067811865476f));
            g_h[(size_t)row*512 + col] = g;
        }
    }
}

// ---------------- kernel 4: gate = softmax(h @ W2 + b2) ----------------
__global__ void gate_kernel(const float* __restrict__ w2,
                            const float* __restrict__ b2) {
    const int rid = blockIdx.x, tid = threadIdx.x;
    float s0 = 0.f, s1 = 0.f;
    for (int m = tid; m < 512; m += 128) {
        float hv = g_h[(size_t)rid*512 + m];
        s0 = fmaf(hv, w2[m*2 + 0], s0);
        s1 = fmaf(hv, w2[m*2 + 1], s1);
    }
    #pragma unroll
    for (int off = 16; off; off >>= 1) {
        s0 += __shfl_xor_sync(0xffffffffu, s0, off);
        s1 += __shfl_xor_sync(0xffffffffu, s1, off);
    }
    __shared__ float r0[4], r1[4];
    const int warp = tid >> 5;
    if ((tid & 31) == 0) { r0[warp] = s0; r1[warp] = s1; }
    __syncthreads();
    if (tid == 0) {
        float l0 = r0[0]+r0[1]+r0[2]+r0[3] + b2[0];
        float l1 = r1[0]+r1[1]+r1[2]+r1[3] + b2[1];
        float m  = fmaxf(l0, l1);
        float e0 = __expf(l0 - m), e1 = __expf(l1 - m);
        float inv = 1.0f / (e0 + e1);
        g_w[rid*2 + 0] = e0 * inv;
        g_w[rid*2 + 1] = e1 * inv;
    }
}

// ---------------- kernel 5: BN stats per d over (B,O) ----------------
__global__ void bnstats_kernel() {
    const int d = blockIdx.x, tid = threadIdx.x;
    float s = 0.f, sq = 0.f;
    for (int j = tid; j < B_*O_; j += 256) {
        int b = j / O_, o = j - b*O_;
        float v = g_V[((size_t)b*D_ + d)*O_ + o];
        s += v;
        sq = fmaf(v, v, sq);
    }
    #pragma unroll
    for (int off = 16; off; off >>= 1) {
        s  += __shfl_xor_sync(0xffffffffu, s,  off);
        sq += __shfl_xor_sync(0xffffffffu, sq, off);
    }
    __shared__ float rs[8], rq[8];
    const int warp = tid >> 5;
    if ((tid & 31) == 0) { rs[warp] = s; rq[warp] = sq; }
    __syncthreads();
    if (tid == 0) {
        float ts = 0.f, tq = 0.f;
        #pragma unroll
        for (int i = 0; i < 8; i++) { ts += rs[i]; tq += rq[i]; }
        float mu  = ts * (1.0f / (B_*O_));
        float var = tq * (1.0f / (B_*O_)) - mu*mu;
        g_mu[d]   = mu;
        g_rstd[d] = rsqrtf(var + 1e-5f);
    }
}

// ---------------- kernel 6: BN apply + gated fusion -> out (B,O,D) ----------------
__global__ void final_kernel(const float* __restrict__ bn_gamma,
                             const float* __restrict__ bn_beta,
                             float* __restrict__ out) {
    const int idx = blockIdx.x * 256 + threadIdx.x;
    if (idx >= B_*O_*D_) return;
    const int d = idx & (D_ - 1);
    const int rest = idx >> 5;
    const int o = rest % O_;
    const int b = rest / O_;
    const int bd = b*D_ + d;
    float v  = g_V[(size_t)bd*O_ + o];
    float y  = fmaf((v - g_mu[d]) * g_rstd[d], bn_gamma[d], bn_beta[d]);
    float ym = g_ymean[(size_t)bd*O_ + o];
    out[idx] = ym * g_w[bd*2 + 0] + y * g_w[bd*2 + 1];
}

// ---------------- launch ----------------
extern "C" void kernel_launch(void* const* d_in, const int* in_sizes, int n_in,
                              void* d_out, int out_size) {
    const float* x       = (const float*)d_in[0];
    const float* x_date  = (const float*)d_in[1];
    const float* y_date  = (const float*)d_in[2];
    const float* mlp_w1  = (const float*)d_in[3];
    const float* mlp_b1  = (const float*)d_in[4];
    const float* mlp_w2  = (const float*)d_in[5];
    const float* mlp_b2  = (const float*)d_in[6];
    const float* bn_gamma= (const float*)d_in[7];
    const float* bn_beta = (const float*)d_in[8];
    float* out = (float*)d_out;

    stats_kernel<<<B_*D_*(K_ + 1), 256>>>(x, x_date);
    attn_kernel<<<B_*D_, 256>>>(x, x_date, y_date);
    mlp1_kernel<<<dim3(DM_/64, (B_*D_)/64), 256>>>(mlp_w1, mlp_b1);
    gate_kernel<<<B_*D_, 128>>>(mlp_w2, mlp_b2);
    bnstats_kernel<<<D_, 256>>>();
    final_kernel<<<(B_*O_*D_ + 255)/256, 256>>>(bn_gamma, bn_beta, out);
}

// round 2
// speedup vs baseline: 1.5125x; 1.5125x over previous
#include <cuda_runtime.h>
#include <math.h>

#define B_  32
#define L_  512
#define D_  32
#define K_  6
#define O_  192
#define DM_ 512

typedef unsigned long long ull;

// ---------------- scratch (device globals) ----------------
__device__ float g_med_true[B_*D_];
__device__ float g_std_true[B_*D_];
__device__ float g_med_map[B_*D_*K_];
__device__ float g_std_map[B_*D_*K_];
__device__ float g_err[B_*D_*L_];      // (bd, l)
__device__ float g_ymean[B_*D_*O_];    // (bd, o)
__device__ float g_V[B_*D_*O_];        // (b,d,o)
__device__ float g_gl[B_*D_*2];        // gate logits (atomic-accumulated)
__device__ float g_mu[D_];
__device__ float g_rstd[D_];

// ---------------- packed f32x2 helpers ----------------
#define MUL2(d,a,b)   asm("mul.rn.f32x2 %0, %1, %2;"      : "=l"(d) : "l"(a), "l"(b))
#define ADD2(d,a,b)   asm("add.rn.f32x2 %0, %1, %2;"      : "=l"(d) : "l"(a), "l"(b))
#define FMA2(d,a,b,c) asm("fma.rn.f32x2 %0, %1, %2, %3;"  : "=l"(d) : "l"(a), "l"(b), "l"(c))
#define PACK2(p,lo,hi)   asm("mov.b64 %0, {%1, %2};" : "=l"(p) : "f"(lo), "f"(hi))
#define UNPACK2(lo,hi,p) asm("mov.b64 {%0, %1}, %2;" : "=f"(lo), "=f"(hi) : "l"(p))
#define EX2(d,s)      asm("ex2.approx.f32 %0, %1;"        : "=f"(d) : "f"(s))

// ---------------- warp-register bitonic sort of 512 elems ----------------
// lane owns contiguous elements e = lane*16 + i  (i = 0..15)
__device__ __forceinline__ void warp_sort512(float v[16], int lane) {
    #pragma unroll
    for (int lsz = 1; lsz <= 9; lsz++) {
        const int size = 1 << lsz;
        // cross-lane strides (s >= 16): partner lane = lane ^ (s>>4)
        #pragma unroll
        for (int s = size >> 1; s >= 16; s >>= 1) {
            const int plane = s >> 4;
            const bool up   = (lane & plane) == 0;
            const bool desc = (lane & (size >> 4)) != 0;   // size >= 32 here
            const bool keepmin = (up != desc);
            #pragma unroll
            for (int i = 0; i < 16; i++) {
                float o = __shfl_xor_sync(0xffffffffu, v[i], plane);
                v[i] = keepmin ? fminf(v[i], o) : fmaxf(v[i], o);
            }
        }
        // in-register strides (s <= 8)
        #pragma unroll
        for (int s = (size >= 32 ? 8 : size >> 1); s >= 1; s >>= 1) {
            #pragma unroll
            for (int i = 0; i < 16; i++) {
                if ((i & s) == 0) {
                    const bool desc = (size >= 16) ? ((lane & (size >> 4)) != 0)
                                                   : ((i & size) != 0);
                    float a = v[i], b = v[i | s];
                    float lo = fminf(a, b), hi = fmaxf(a, b);
                    v[i]     = desc ? hi : lo;
                    v[i | s] = desc ? lo : hi;
                }
            }
        }
    }
}

// ---------------- kernel 1: robust stats, one warp per sequence ----------------
// grid = B*D blocks, 224 threads = 7 warps: warps 0..5 sort x_date[b,:,d,k],
// warp 6 sorts x[b,:,d]. Also zero-inits gate logit accumulators.
__global__ void __launch_bounds__(224) stats_kernel(const float* __restrict__ x,
                                                    const float* __restrict__ x_date) {
    const int bd = blockIdx.x, tid = threadIdx.x;
    const int b = bd >> 5, d = bd & 31;
    const int warp = tid >> 5, lane = tid & 31;

    if (bd < 16 && tid < 128) g_gl[bd*128 + tid] = 0.0f;

    float v[16];
    if (warp < 6) {
        const float* p = x_date + ((size_t)(b*L_)*D_ + d)*(size_t)K_ + warp;
        #pragma unroll
        for (int i = 0; i < 16; i++) v[i] = p[(size_t)(lane*16 + i) * (D_*K_)];
    } else {
        const float* p = x + (size_t)(b*L_)*D_ + d;
        #pragma unroll
        for (int i = 0; i < 16; i++) v[i] = p[(size_t)(lane*16 + i) * D_];
    }

    warp_sort512(v, lane);

    const float e127 = __shfl_sync(0xffffffffu, v[15], 7);
    const float e128 = __shfl_sync(0xffffffffu, v[0],  8);
    const float e255 = __shfl_sync(0xffffffffu, v[15], 15);
    const float e383 = __shfl_sync(0xffffffffu, v[15], 23);
    const float e384 = __shfl_sync(0xffffffffu, v[0],  24);

    if (lane == 0) {
        const float med = e255;                                // torch lower-median
        const float q75 = e383 + 0.25f * (e384 - e383);        // pos 383.25
        const float q25 = e127 + 0.75f * (e128 - e127);        // pos 127.75
        const float sd  = q75 - q25 + 1e-6f;
        if (warp < 6) { g_med_map[bd*K_ + warp] = med; g_std_map[bd*K_ + warp] = sd; }
        else          { g_med_true[bd] = med;          g_std_true[bd] = sd; }
    }
}

// ---------------- kernel 2: fused map + single-pass softmax attention ----------------
// one block per (b,d); 8 warps; each warp owns 24 o's in 3 groups of 8.
// No max-subtraction (scores bounded << 88); exp folded to bare ex2.approx.
__global__ void __launch_bounds__(256) attn_kernel(const float* __restrict__ x,
                                                   const float* __restrict__ x_date,
                                                   const float* __restrict__ y_date) {
    __shared__ ull   sxd2[K_][L_];     // mapped x_date duplicated into both f32x2 halves
    __shared__ float syd[O_][K_];      // mapped y_date * (1/sqrt(6) * log2(e))
    __shared__ ull   sx2[L_];          // x duplicated
    __shared__ float ssc[K_], ssh[K_];

    const int bd = blockIdx.x, tid = threadIdx.x;
    const int b = bd / D_, d = bd % D_;
    const float CSC = 0.408248290463863f * 1.4426950408889634f;  // 1/sqrt6 * log2e
    const float INV6C = (1.0f/6.0f) / CSC;

    if (tid < K_) {
        float st = g_std_true[bd], mt = g_med_true[bd];
        float smv = g_std_map[bd*K_ + tid], mm = g_med_map[bd*K_ + tid];
        float sc = st / smv;
        ssc[tid] = sc;
        ssh[tid] = mt - mm * sc;
    }
    for (int l = tid; l < L_; l += 256) {
        float xv = x[((size_t)b*L_ + l)*D_ + d];
        ull p; PACK2(p, xv, xv);
        sx2[l] = p;
    }
    __syncthreads();

    for (int i = tid; i < L_*K_; i += 256) {
        int l = i / K_, k = i - l*K_;
        float v = x_date[(((size_t)b*L_ + l)*D_ + d)*(size_t)K_ + k];
        float m = fmaf(v, ssc[k], ssh[k]);
        ull p; PACK2(p, m, m);
        sxd2[k][l] = p;
    }
    for (int i = tid; i < O_*K_; i += 256) {
        int o = i / K_, k = i - o*K_;
        float v = y_date[(((size_t)b*O_ + o)*D_ + d)*(size_t)K_ + k];
        syd[o][k] = fmaf(v, ssc[k], ssh[k]) * CSC;
    }
    __syncthreads();

    // err = x - mean_k(x_date_map);  ymean = mean_k(y_date_map) (undo CSC scale)
    for (int l = tid; l < L_; l += 256) {
        float s = 0.f;
        #pragma unroll
        for (int k = 0; k < K_; k++) s += ((const float2*)&sxd2[k][l])->x;
        float xv = ((const float2*)&sx2[l])->x;
        g_err[(size_t)bd*L_ + l] = xv - s * (1.0f/6.0f);
    }
    for (int o = tid; o < O_; o += 256) {
        float s = syd[o][0]+syd[o][1]+syd[o][2]+syd[o][3]+syd[o][4]+syd[o][5];
        g_ymean[(size_t)bd*O_ + o] = s * INV6C;
    }

    const int warp = tid >> 5, lane = tid & 31;

    for (int og = 0; og < 3; og++) {
        const int o0 = warp*24 + og*8;
        ull y2[4][K_];
        #pragma unroll
        for (int p = 0; p < 4; p++)
            #pragma unroll
            for (int k = 0; k < K_; k++)
                PACK2(y2[p][k], syd[o0 + 2*p][k], syd[o0 + 2*p + 1][k]);

        ull sum2[4] = {0,0,0,0};   // bitwise zero == (0.f, 0.f)
        ull vs2[4]  = {0,0,0,0};

        #pragma unroll
        for (int r = 0; r < 16; r++) {
            const int l = lane + (r << 5);
            ull xk0 = sxd2[0][l], xk1 = sxd2[1][l], xk2 = sxd2[2][l];
            ull xk3 = sxd2[3][l], xk4 = sxd2[4][l], xk5 = sxd2[5][l];
            const ull xl2 = sx2[l];
            #pragma unroll
            for (int p = 0; p < 4; p++) {
                ull acc;
                MUL2(acc, xk0, y2[p][0]);
                FMA2(acc, xk1, y2[p][1], acc);
                FMA2(acc, xk2, y2[p][2], acc);
                FMA2(acc, xk3, y2[p][3], acc);
                FMA2(acc, xk4, y2[p][4], acc);
                FMA2(acc, xk5, y2[p][5], acc);
                float s0, s1; UNPACK2(s0, s1, acc);
                float p0, p1; EX2(p0, s0); EX2(p1, s1);
                ull pp; PACK2(pp, p0, p1);
                ADD2(sum2[p], sum2[p], pp);
                FMA2(vs2[p], pp, xl2, vs2[p]);
            }
        }
        #pragma unroll
        for (int p = 0; p < 4; p++) {
            #pragma unroll
            for (int off = 16; off; off >>= 1) {
                ull o1 = __shfl_xor_sync(0xffffffffu, sum2[p], off);
                ADD2(sum2[p], sum2[p], o1);
                ull o2 = __shfl_xor_sync(0xffffffffu, vs2[p], off);
                ADD2(vs2[p], vs2[p], o2);
            }
        }
        if (lane == 0) {
            #pragma unroll
            for (int p = 0; p < 4; p++) {
                float slo, shi, vlo, vhi;
                UNPACK2(slo, shi, sum2[p]);
                UNPACK2(vlo, vhi, vs2[p]);
                g_V[(size_t)bd*O_ + o0 + 2*p]     = vlo / slo;
                g_V[(size_t)bd*O_ + o0 + 2*p + 1] = vhi / shi;
            }
        }
    }
}

// ---------------- kernel 3: GEMM + gelu + fused gate-logit accumulation ----------------
__global__ void __launch_bounds__(256) mlp1_kernel(const float* __restrict__ w1,
                                                   const float* __restrict__ b1,
                                                   const float* __restrict__ w2) {
    __shared__ float Es[64][17];
    __shared__ __align__(16) float Ws[16][64];
    const int tx = threadIdx.x & 15, ty = threadIdx.x >> 4;
    const int row0 = blockIdx.y * 64, col0 = blockIdx.x * 64;
    float acc[4][4] = {};

    for (int k0 = 0; k0 < 512; k0 += 16) {
        __syncthreads();
        #pragma unroll
        for (int it = 0; it < 4; it++) {
            int idx = threadIdx.x + it*256;
            int r  = idx >> 4, kk = idx & 15;
            Es[r][kk] = g_err[(size_t)(row0 + r)*512 + k0 + kk];
            int kw = idx >> 6, c = idx & 63;
            Ws[kw][c] = w1[(size_t)(k0 + kw)*512 + col0 + c];
        }
        __syncthreads();
        #pragma unroll
        for (int kk = 0; kk < 16; kk++) {
            float a0 = Es[ty*4+0][kk], a1 = Es[ty*4+1][kk];
            float a2 = Es[ty*4+2][kk], a3 = Es[ty*4+3][kk];
            const float4 bq = *reinterpret_cast<const float4*>(&Ws[kk][tx*4]);
            acc[0][0]=fmaf(a0,bq.x,acc[0][0]); acc[0][1]=fmaf(a0,bq.y,acc[0][1]);
            acc[0][2]=fmaf(a0,bq.z,acc[0][2]); acc[0][3]=fmaf(a0,bq.w,acc[0][3]);
            acc[1][0]=fmaf(a1,bq.x,acc[1][0]); acc[1][1]=fmaf(a1,bq.y,acc[1][1]);
            acc[1][2]=fmaf(a1,bq.z,acc[1][2]); acc[1][3]=fmaf(a1,bq.w,acc[1][3]);
            acc[2][0]=fmaf(a2,bq.x,acc[2][0]); acc[2][1]=fmaf(a2,bq.y,acc[2][1]);
            acc[2][2]=fmaf(a2,bq.z,acc[2][2]); acc[2][3]=fmaf(a2,bq.w,acc[2][3]);
            acc[3][0]=fmaf(a3,bq.x,acc[3][0]); acc[3][1]=fmaf(a3,bq.y,acc[3][1]);
            acc[3][2]=fmaf(a3,bq.z,acc[3][2]); acc[3][3]=fmaf(a3,bq.w,acc[3][3]);
        }
    }
    #pragma unroll
    for (int i = 0; i < 4; i++) {
        const int row = row0 + ty*4 + i;
        float p0 = 0.f, p1 = 0.f;
        #pragma unroll
        for (int j = 0; j < 4; j++) {
            const int col = col0 + tx*4 + j;
            float v = acc[i][j] + b1[col];
            float g = 0.5f * v * (1.0f + erff(v * 0.7071067811865476f));
            p0 = fmaf(g, w2[col*2 + 0], p0);
            p1 = fmaf(g, w2[col*2 + 1], p1);
        }
        // reduce over the 16 tx-lanes (lanes tx + (ty&1)*16 within the warp)
        #pragma unroll
        for (int off = 8; off; off >>= 1) {
            p0 += __shfl_xor_sync(0xffffffffu, p0, off);
            p1 += __shfl_xor_sync(0xffffffffu, p1, off);
        }
        if (tx == 0) {
            atomicAdd(&g_gl[row*2 + 0], p0);
            atomicAdd(&g_gl[row*2 + 1], p1);
        }
    }
}

// ---------------- kernel 4: BN stats per d over (B,O) ----------------
__global__ void bnstats_kernel() {
    const int d = blockIdx.x, tid = threadIdx.x;
    float s = 0.f, sq = 0.f;
    for (int j = tid; j < B_*O_; j += 256) {
        int b = j / O_, o = j - b*O_;
        float v = g_V[((size_t)b*D_ + d)*O_ + o];
        s += v;
        sq = fmaf(v, v, sq);
    }
    #pragma unroll
    for (int off = 16; off; off >>= 1) {
        s  += __shfl_xor_sync(0xffffffffu, s,  off);
        sq += __shfl_xor_sync(0xffffffffu, sq, off);
    }
    __shared__ float rs[8], rq[8];
    const int warp = tid >> 5;
    if ((tid & 31) == 0) { rs[warp] = s; rq[warp] = sq; }
    __syncthreads();
    if (tid == 0) {
        float ts = 0.f, tq = 0.f;
        #pragma unroll
        for (int i = 0; i < 8; i++) { ts += rs[i]; tq += rq[i]; }
        float mu  = ts * (1.0f / (B_*O_));
        float var = tq * (1.0f / (B_*O_)) - mu*mu;
        g_mu[d]   = mu;
        g_rstd[d] = rsqrtf(var + 1e-5f);
    }
}

// ---------------- kernel 5: BN apply + inline gate softmax + fusion ----------------
__global__ void final_kernel(const float* __restrict__ bn_gamma,
                             const float* __restrict__ bn_beta,
                             const float* __restrict__ b2,
                             float* __restrict__ out) {
    const int idx = blockIdx.x * 256 + threadIdx.x;
    if (idx >= B_*O_*D_) return;
    const int d = idx & (D_ - 1);
    const int rest = idx >> 5;
    const int o = rest % O_;
    const int b = rest / O_;
    const int bd = b*D_ + d;

    float l0 = g_gl[bd*2 + 0] + b2[0];
    float l1 = g_gl[bd*2 + 1] + b2[1];
    float m  = fmaxf(l0, l1);
    float e0 = __expf(l0 - m), e1 = __expf(l1 - m);
    float inv = 1.0f / (e0 + e1);

    float v  = g_V[(size_t)bd*O_ + o];
    float y  = fmaf((v - g_mu[d]) * g_rstd[d], bn_gamma[d], bn_beta[d]);
    float ym = g_ymean[(size_t)bd*O_ + o];
    out[idx] = ym * (e0 * inv) + y * (e1 * inv);
}

// ---------------- launch ----------------
extern "C" void kernel_launch(void* const* d_in, const int* in_sizes, int n_in,
                              void* d_out, int out_size) {
    const float* x       = (const float*)d_in[0];
    const float* x_date  = (const float*)d_in[1];
    const float* y_date  = (const float*)d_in[2];
    const float* mlp_w1  = (const float*)d_in[3];
    const float* mlp_b1  = (const float*)d_in[4];
    const float* mlp_w2  = (const float*)d_in[5];
    const float* mlp_b2  = (const float*)d_in[6];
    const float* bn_gamma= (const float*)d_in[7];
    const float* bn_beta = (const float*)d_in[8];
    float* out = (float*)d_out;

    stats_kernel<<<B_*D_, 224>>>(x, x_date);
    attn_kernel<<<B_*D_, 256>>>(x, x_date, y_date);
    mlp1_kernel<<<dim3(DM_/64, (B_*D_)/64), 256>>>(mlp_w1, mlp_b1, mlp_w2);
    bnstats_kernel<<<D_, 256>>>();
    final_kernel<<<(B_*O_*D_ + 255)/256, 256>>>(bn_gamma, bn_beta, mlp_b2, out);
}

// round 3
// speedup vs baseline: 1.5906x; 1.0517x over previous
#include <cuda_runtime.h>
#include <math.h>

#define B_  32
#define L_  512
#define D_  32
#define K_  6
#define O_  192
#define DM_ 512

typedef unsigned long long ull;

// ---------------- scratch (device globals) ----------------
__device__ float g_err[B_*D_*L_];      // (bd, l)
__device__ float g_ymean[B_*D_*O_];    // (bd, o)
__device__ float g_V[B_*D_*O_];        // (b,d,o)
__device__ float g_gl[B_*D_*2];        // gate logits (atomic-accumulated)
__device__ float g_psum[B_*D_];        // per-block BN partial sum
__device__ float g_psq[B_*D_];         // per-block BN partial sumsq
__device__ float g_mu[D_];
__device__ float g_rstd[D_];

// ---------------- packed f32x2 helpers ----------------
#define MUL2(d,a,b)   asm("mul.rn.f32x2 %0, %1, %2;"      : "=l"(d) : "l"(a), "l"(b))
#define ADD2(d,a,b)   asm("add.rn.f32x2 %0, %1, %2;"      : "=l"(d) : "l"(a), "l"(b))
#define FMA2(d,a,b,c) asm("fma.rn.f32x2 %0, %1, %2, %3;"  : "=l"(d) : "l"(a), "l"(b), "l"(c))
#define PACK2(p,lo,hi)   asm("mov.b64 %0, {%1, %2};" : "=l"(p) : "f"(lo), "f"(hi))
#define UNPACK2(lo,hi,p) asm("mov.b64 {%0, %1}, %2;" : "=f"(lo), "=f"(hi) : "l"(p))
#define EX2(d,s)      asm("ex2.approx.f32 %0, %1;"        : "=f"(d) : "f"(s))

// ---------------- warp-register bitonic sort of 512 elems ----------------
// position p = lane*16 + i ; initial VALUE placement is arbitrary (network sorts positions)
__device__ __forceinline__ void warp_sort512(float v[16], int lane) {
    #pragma unroll
    for (int lsz = 1; lsz <= 9; lsz++) {
        const int size = 1 << lsz;
        #pragma unroll
        for (int s = size >> 1; s >= 16; s >>= 1) {
            const int plane = s >> 4;
            const bool up   = (lane & plane) == 0;
            const bool desc = (lane & (size >> 4)) != 0;
            const bool keepmin = (up != desc);
            #pragma unroll
            for (int i = 0; i < 16; i++) {
                float o = __shfl_xor_sync(0xffffffffu, v[i], plane);
                v[i] = keepmin ? fminf(v[i], o) : fmaxf(v[i], o);
            }
        }
        #pragma unroll
        for (int s = (size >= 32 ? 8 : size >> 1); s >= 1; s >>= 1) {
            #pragma unroll
            for (int i = 0; i < 16; i++) {
                if ((i & s) == 0) {
                    const bool desc = (size >= 16) ? ((lane & (size >> 4)) != 0)
                                                   : ((i & size) != 0);
                    float a = v[i], b = v[i | s];
                    float lo = fminf(a, b), hi = fmaxf(a, b);
                    v[i]     = desc ? hi : lo;
                    v[i | s] = desc ? lo : hi;
                }
            }
        }
    }
}

// ---------------- kernel 1: fused stats + map + attention + BN partials ----------------
// one block per (b,d); 256 threads = 8 warps.
__global__ void __launch_bounds__(256) fused_kernel(const float* __restrict__ x,
                                                    const float* __restrict__ x_date,
                                                    const float* __restrict__ y_date) {
    __shared__ float sraw[K_][L_];     // raw x_date column (12 KB)
    __shared__ float sxraw[L_];        // raw x column (2 KB)
    __shared__ ull   sxd2[K_][L_];     // mapped x_date dup'd into f32x2 halves (24 KB)
    __shared__ float syd[O_][K_];      // mapped y_date * (1/sqrt6 * log2e) (4.5 KB)
    __shared__ ull   sx2[L_];          // x dup'd (4 KB)
    __shared__ float sV[O_];           // V values for BN partial (768 B)
    __shared__ float smed[8], ssd[8];
    __shared__ float ssc[K_], ssh[K_];

    const int bd = blockIdx.x, tid = threadIdx.x;
    const int b = bd >> 5, d = bd & 31;
    const int warp = tid >> 5, lane = tid & 31;
    const float CSC = 0.408248290463863f * 1.4426950408889634f;  // 1/sqrt6 * log2e
    const float INV6C = (1.0f/6.0f) / CSC;

    // zero gate-logit accumulators (mlp1 runs strictly after this kernel)
    if (bd < 8) g_gl[bd*256 + tid] = 0.0f;

    // ---- stage raw data into smem (near-coalesced 24B chunks) ----
    const float* xd_base = x_date + (size_t)b*L_*D_*K_ + (size_t)d*K_;
    for (int i = tid; i < L_*K_; i += 256) {
        int l = i / K_, k = i - l*K_;
        sraw[k][l] = xd_base[(size_t)l*(D_*K_) + k];
    }
    for (int l = tid; l < L_; l += 256)
        sxraw[l] = x[((size_t)b*L_ + l)*D_ + d];
    __syncthreads();

    // ---- sort: warps 0..5 -> x_date[:,k], warp 6 -> x ----
    if (warp < 7) {
        float v[16];
        const float* src = (warp < 6) ? sraw[warp] : sxraw;
        #pragma unroll
        for (int i = 0; i < 16; i++) v[i] = src[lane + 32*i];   // conflict-free
        warp_sort512(v, lane);
        const float e127 = __shfl_sync(0xffffffffu, v[15], 7);
        const float e128 = __shfl_sync(0xffffffffu, v[0],  8);
        const float e255 = __shfl_sync(0xffffffffu, v[15], 15);
        const float e383 = __shfl_sync(0xffffffffu, v[15], 23);
        const float e384 = __shfl_sync(0xffffffffu, v[0],  24);
        if (lane == 0) {
            const float q75 = e383 + 0.25f * (e384 - e383);    // pos 383.25
            const float q25 = e127 + 0.75f * (e128 - e127);    // pos 127.75
            smed[warp] = e255;                                 // torch lower-median
            ssd[warp]  = q75 - q25 + 1e-6f;
        }
    }
    __syncthreads();
    if (tid < K_) {
        float sc = ssd[6] / ssd[tid];
        ssc[tid] = sc;
        ssh[tid] = smed[6] - smed[tid] * sc;
    }
    __syncthreads();

    // ---- map + pack ----
    for (int l = tid; l < L_; l += 256) {
        float xv = sxraw[l];
        ull p; PACK2(p, xv, xv);
        sx2[l] = p;
    }
    #pragma unroll
    for (int k = 0; k < K_; k++) {
        const float sck = ssc[k], shk = ssh[k];
        for (int l = tid; l < L_; l += 256) {
            float m = fmaf(sraw[k][l], sck, shk);
            ull p; PACK2(p, m, m);
            sxd2[k][l] = p;
        }
    }
    const float* yd_base = y_date + (size_t)b*O_*D_*K_ + (size_t)d*K_;
    for (int i = tid; i < O_*K_; i += 256) {
        int o = i / K_, k = i - o*K_;
        float v = yd_base[(size_t)o*(D_*K_) + k];
        syd[o][k] = fmaf(v, ssc[k], ssh[k]) * CSC;
    }
    __syncthreads();

    // ---- err = x - mean_k(map) ; ymean = mean_k(y_map) ----
    for (int l = tid; l < L_; l += 256) {
        float s = 0.f;
        #pragma unroll
        for (int k = 0; k < K_; k++) s += ((const float2*)&sxd2[k][l])->x;
        g_err[(size_t)bd*L_ + l] = sxraw[l] - s * (1.0f/6.0f);
    }
    for (int o = tid; o < O_; o += 256) {
        float s = syd[o][0]+syd[o][1]+syd[o][2]+syd[o][3]+syd[o][4]+syd[o][5];
        g_ymean[(size_t)bd*O_ + o] = s * INV6C;
    }

    // ---- single-pass softmax attention (no max-subtraction; scores bounded) ----
    for (int og = 0; og < 3; og++) {
        const int o0 = warp*24 + og*8;
        ull y2[4][K_];
        #pragma unroll
        for (int p = 0; p < 4; p++)
            #pragma unroll
            for (int k = 0; k < K_; k++)
                PACK2(y2[p][k], syd[o0 + 2*p][k], syd[o0 + 2*p + 1][k]);

        ull sum2[4] = {0,0,0,0};
        ull vs2[4]  = {0,0,0,0};

        #pragma unroll
        for (int r = 0; r < 16; r++) {
            const int l = lane + (r << 5);
            ull xk0 = sxd2[0][l], xk1 = sxd2[1][l], xk2 = sxd2[2][l];
            ull xk3 = sxd2[3][l], xk4 = sxd2[4][l], xk5 = sxd2[5][l];
            const ull xl2 = sx2[l];
            #pragma unroll
            for (int p = 0; p < 4; p++) {
                ull acc;
                MUL2(acc, xk0, y2[p][0]);
                FMA2(acc, xk1, y2[p][1], acc);
                FMA2(acc, xk2, y2[p][2], acc);
                FMA2(acc, xk3, y2[p][3], acc);
                FMA2(acc, xk4, y2[p][4], acc);
                FMA2(acc, xk5, y2[p][5], acc);
                float s0, s1; UNPACK2(s0, s1, acc);
                float p0, p1; EX2(p0, s0); EX2(p1, s1);
                ull pp; PACK2(pp, p0, p1);
                ADD2(sum2[p], sum2[p], pp);
                FMA2(vs2[p], pp, xl2, vs2[p]);
            }
        }
        #pragma unroll
        for (int p = 0; p < 4; p++) {
            #pragma unroll
            for (int off = 16; off; off >>= 1) {
                ull o1 = __shfl_xor_sync(0xffffffffu, sum2[p], off);
                ADD2(sum2[p], sum2[p], o1);
                ull o2 = __shfl_xor_sync(0xffffffffu, vs2[p], off);
                ADD2(vs2[p], vs2[p], o2);
            }
        }
        if (lane == 0) {
            #pragma unroll
            for (int p = 0; p < 4; p++) {
                float slo, shi, vlo, vhi;
                UNPACK2(slo, shi, sum2[p]);
                UNPACK2(vlo, vhi, vs2[p]);
                float va = vlo / slo, vb = vhi / shi;
                g_V[(size_t)bd*O_ + o0 + 2*p]     = va;
                g_V[(size_t)bd*O_ + o0 + 2*p + 1] = vb;
                sV[o0 + 2*p]     = va;
                sV[o0 + 2*p + 1] = vb;
            }
        }
    }
    __syncthreads();

    // ---- BN partials over this block's 192 o-values ----
    if (warp == 0) {
        float s = 0.f, sq = 0.f;
        for (int o = lane; o < O_; o += 32) {
            float v = sV[o];
            s += v;
            sq = fmaf(v, v, sq);
        }
        #pragma unroll
        for (int off = 16; off; off >>= 1) {
            s  += __shfl_xor_sync(0xffffffffu, s,  off);
            sq += __shfl_xor_sync(0xffffffffu, sq, off);
        }
        if (lane == 0) { g_psum[bd] = s; g_psq[bd] = sq; }
    }
}

// ---------------- kernel 2: GEMM + gelu + fused gate-logit accumulation ----------------
__global__ void __launch_bounds__(256) mlp1_kernel(const float* __restrict__ w1,
                                                   const float* __restrict__ b1,
                                                   const float* __restrict__ w2) {
    __shared__ float Es[64][17];
    __shared__ __align__(16) float Ws[16][64];
    const int tx = threadIdx.x & 15, ty = threadIdx.x >> 4;
    const int row0 = blockIdx.y * 64, col0 = blockIdx.x * 64;
    float acc[4][4] = {};

    for (int k0 = 0; k0 < 512; k0 += 16) {
        __syncthreads();
        #pragma unroll
        for (int it = 0; it < 4; it++) {
            int idx = threadIdx.x + it*256;
            int r  = idx >> 4, kk = idx & 15;
            Es[r][kk] = g_err[(size_t)(row0 + r)*512 + k0 + kk];
            int kw = idx >> 6, c = idx & 63;
            Ws[kw][c] = w1[(size_t)(k0 + kw)*512 + col0 + c];
        }
        __syncthreads();
        #pragma unroll
        for (int kk = 0; kk < 16; kk++) {
            float a0 = Es[ty*4+0][kk], a1 = Es[ty*4+1][kk];
            float a2 = Es[ty*4+2][kk], a3 = Es[ty*4+3][kk];
            const float4 bq = *reinterpret_cast<const float4*>(&Ws[kk][tx*4]);
            acc[0][0]=fmaf(a0,bq.x,acc[0][0]); acc[0][1]=fmaf(a0,bq.y,acc[0][1]);
            acc[0][2]=fmaf(a0,bq.z,acc[0][2]); acc[0][3]=fmaf(a0,bq.w,acc[0][3]);
            acc[1][0]=fmaf(a1,bq.x,acc[1][0]); acc[1][1]=fmaf(a1,bq.y,acc[1][1]);
            acc[1][2]=fmaf(a1,bq.z,acc[1][2]); acc[1][3]=fmaf(a1,bq.w,acc[1][3]);
            acc[2][0]=fmaf(a2,bq.x,acc[2][0]); acc[2][1]=fmaf(a2,bq.y,acc[2][1]);
            acc[2][2]=fmaf(a2,bq.z,acc[2][2]); acc[2][3]=fmaf(a2,bq.w,acc[2][3]);
            acc[3][0]=fmaf(a3,bq.x,acc[3][0]); acc[3][1]=fmaf(a3,bq.y,acc[3][1]);
            acc[3][2]=fmaf(a3,bq.z,acc[3][2]); acc[3][3]=fmaf(a3,bq.w,acc[3][3]);
        }
    }
    #pragma unroll
    for (int i = 0; i < 4; i++) {
        const int row = row0 + ty*4 + i;
        float p0 = 0.f, p1 = 0.f;
        #pragma unroll
        for (int j = 0; j < 4; j++) {
            const int col = col0 + tx*4 + j;
            float v = acc[i][j] + b1[col];
            float g = 0.5f * v * (1.0f + erff(v * 0.7071067811865476f));
            p0 = fmaf(g, w2[col*2 + 0], p0);
            p1 = fmaf(g, w2[col*2 + 1], p1);
        }
        #pragma unroll
        for (int off = 8; off; off >>= 1) {
            p0 += __shfl_xor_sync(0xffffffffu, p0, off);
            p1 += __shfl_xor_sync(0xffffffffu, p1, off);
        }
        if (tx == 0) {
            atomicAdd(&g_gl[row*2 + 0], p0);
            atomicAdd(&g_gl[row*2 + 1], p1);
        }
    }
}

// ---------------- kernel 3: BN final stats (1 block, 32 warps = 32 d's) ----------------
__global__ void bnfinal_kernel() {
    const int d = threadIdx.x >> 5, lane = threadIdx.x & 31;   // lane = b
    float s  = g_psum[lane*D_ + d];
    float sq = g_psq[lane*D_ + d];
    #pragma unroll
    for (int off = 16; off; off >>= 1) {
        s  += __shfl_xor_sync(0xffffffffu, s,  off);
        sq += __shfl_xor_sync(0xffffffffu, sq, off);
    }
    if (lane == 0) {
        float mu  = s * (1.0f / (B_*O_));
        float var = sq * (1.0f / (B_*O_)) - mu*mu;
        g_mu[d]   = mu;
        g_rstd[d] = rsqrtf(var + 1e-5f);
    }
}

// ---------------- kernel 4: BN apply + inline gate softmax + fusion ----------------
__global__ void final_kernel(const float* __restrict__ bn_gamma,
                             const float* __restrict__ bn_beta,
                             const float* __restrict__ b2,
                             float* __restrict__ out) {
    const int idx = blockIdx.x * 256 + threadIdx.x;
    if (idx >= B_*O_*D_) return;
    const int d = idx & (D_ - 1);
    const int rest = idx >> 5;
    const int o = rest % O_;
    const int b = rest / O_;
    const int bd = b*D_ + d;

    float l0 = g_gl[bd*2 + 0] + b2[0];
    float l1 = g_gl[bd*2 + 1] + b2[1];
    float m  = fmaxf(l0, l1);
    float e0 = __expf(l0 - m), e1 = __expf(l1 - m);
    float inv = 1.0f / (e0 + e1);

    float v  = g_V[(size_t)bd*O_ + o];
    float y  = fmaf((v - g_mu[d]) * g_rstd[d], bn_gamma[d], bn_beta[d]);
    float ym = g_ymean[(size_t)bd*O_ + o];
    out[idx] = ym * (e0 * inv) + y * (e1 * inv);
}

// ---------------- launch ----------------
extern "C" void kernel_launch(void* const* d_in, const int* in_sizes, int n_in,
                              void* d_out, int out_size) {
    const float* x       = (const float*)d_in[0];
    const float* x_date  = (const float*)d_in[1];
    const float* y_date  = (const float*)d_in[2];
    const float* mlp_w1  = (const float*)d_in[3];
    const float* mlp_b1  = (const float*)d_in[4];
    const float* mlp_w2  = (const float*)d_in[5];
    const float* mlp_b2  = (const float*)d_in[6];
    const float* bn_gamma= (const float*)d_in[7];
    const float* bn_beta = (const float*)d_in[8];
    float* out = (float*)d_out;

    fused_kernel<<<B_*D_, 256>>>(x, x_date, y_date);
    bnfinal_kernel<<<1, 1024>>>();
    mlp1_kernel<<<dim3(DM_/64, (B_*D_)/64), 256>>>(mlp_w1, mlp_b1, mlp_w2);
    final_kernel<<<(B_*O_*D_ + 255)/256, 256>>>(bn_gamma, bn_beta, mlp_b2, out);
}

// round 4
// speedup vs baseline: 1.7141x; 1.0776x over previous
#include <cuda_runtime.h>
#include <math.h>

#define B_  32
#define L_  512
#define D_  32
#define K_  6
#define O_  192
#define DM_ 512

typedef unsigned long long ull;

// ---------------- scratch (device globals) ----------------
__device__ float g_err[B_*D_*L_];      // (bd, l)
__device__ float g_ymean[B_*D_*O_];    // (bd, o)
__device__ float g_V[B_*D_*O_];        // (b,d,o)
__device__ float g_gl[B_*D_*2];        // gate logits (atomic-accumulated)
__device__ float g_psum[B_*D_];        // per-block BN partial sum
__device__ float g_psq[B_*D_];         // per-block BN partial sumsq
__device__ float g_mu[D_];
__device__ float g_rstd[D_];

// ---------------- packed f32x2 helpers ----------------
#define MUL2(d,a,b)   asm("mul.rn.f32x2 %0, %1, %2;"      : "=l"(d) : "l"(a), "l"(b))
#define ADD2(d,a,b)   asm("add.rn.f32x2 %0, %1, %2;"      : "=l"(d) : "l"(a), "l"(b))
#define FMA2(d,a,b,c) asm("fma.rn.f32x2 %0, %1, %2, %3;"  : "=l"(d) : "l"(a), "l"(b), "l"(c))
#define PACK2(p,lo,hi)   asm("mov.b64 %0, {%1, %2};" : "=l"(p) : "f"(lo), "f"(hi))
#define UNPACK2(lo,hi,p) asm("mov.b64 {%0, %1}, %2;" : "=f"(lo), "=f"(hi) : "l"(p))
#define EX2(d,s)      asm("ex2.approx.f32 %0, %1;"        : "=f"(d) : "f"(s))

// ---------------- warp-register bitonic sort of 512 elems ----------------
__device__ __forceinline__ void warp_sort512(float v[16], int lane) {
    #pragma unroll
    for (int lsz = 1; lsz <= 9; lsz++) {
        const int size = 1 << lsz;
        #pragma unroll
        for (int s = size >> 1; s >= 16; s >>= 1) {
            const int plane = s >> 4;
            const bool up   = (lane & plane) == 0;
            const bool desc = (lane & (size >> 4)) != 0;
            const bool keepmin = (up != desc);
            #pragma unroll
            for (int i = 0; i < 16; i++) {
                float o = __shfl_xor_sync(0xffffffffu, v[i], plane);
                v[i] = keepmin ? fminf(v[i], o) : fmaxf(v[i], o);
            }
        }
        #pragma unroll
        for (int s = (size >= 32 ? 8 : size >> 1); s >= 1; s >>= 1) {
            #pragma unroll
            for (int i = 0; i < 16; i++) {
                if ((i & s) == 0) {
                    const bool desc = (size >= 16) ? ((lane & (size >> 4)) != 0)
                                                   : ((i & size) != 0);
                    float a = v[i], b = v[i | s];
                    float lo = fminf(a, b), hi = fmaxf(a, b);
                    v[i]     = desc ? hi : lo;
                    v[i | s] = desc ? lo : hi;
                }
            }
        }
    }
}

// ---------------- kernel 1: fused stats + map + attention + BN partials ----------------
// one block per (b,d); 256 threads = 8 warps. ~20 KB smem, reg-capped for 3 blocks/SM.
__global__ void __launch_bounds__(256, 3) fused_kernel(const float* __restrict__ x,
                                                       const float* __restrict__ x_date,
                                                       const float* __restrict__ y_date) {
    __shared__ float sxd[K_][L_];      // raw x_date, mapped IN PLACE (12 KB)
    __shared__ float sx[L_];           // x column (2 KB)
    __shared__ float syd[O_][K_];      // mapped y_date * (1/sqrt6*log2e) (4.5 KB)
    __shared__ float sV[O_];           // V for BN partial
    __shared__ float smed[8], ssd[8];
    __shared__ float ssc[K_], ssh[K_];

    const int bd = blockIdx.x, tid = threadIdx.x;
    const int b = bd >> 5, d = bd & 31;
    const int warp = tid >> 5, lane = tid & 31;
    const float CSC = 0.408248290463863f * 1.4426950408889634f;  // 1/sqrt6 * log2e
    const float INV6C = (1.0f/6.0f) / CSC;

    // zero gate-logit accumulators (mlp1 runs strictly after this kernel)
    if (bd < 8) g_gl[bd*256 + tid] = 0.0f;

    // ---- stage raw data into smem ----
    const float* xd_base = x_date + (size_t)b*L_*D_*K_ + (size_t)d*K_;
    for (int i = tid; i < L_*K_; i += 256) {
        int l = i / K_, k = i - l*K_;
        sxd[k][l] = xd_base[(size_t)l*(D_*K_) + k];
    }
    for (int l = tid; l < L_; l += 256)
        sx[l] = x[((size_t)b*L_ + l)*D_ + d];
    __syncthreads();

    // ---- sort: warps 0..5 -> x_date[:,k], warp 6 -> x ----
    if (warp < 7) {
        float v[16];
        const float* src = (warp < 6) ? sxd[warp] : sx;
        #pragma unroll
        for (int i = 0; i < 16; i++) v[i] = src[lane + 32*i];
        warp_sort512(v, lane);
        const float e127 = __shfl_sync(0xffffffffu, v[15], 7);
        const float e128 = __shfl_sync(0xffffffffu, v[0],  8);
        const float e255 = __shfl_sync(0xffffffffu, v[15], 15);
        const float e383 = __shfl_sync(0xffffffffu, v[15], 23);
        const float e384 = __shfl_sync(0xffffffffu, v[0],  24);
        if (lane == 0) {
            const float q75 = e383 + 0.25f * (e384 - e383);
            const float q25 = e127 + 0.75f * (e128 - e127);
            smed[warp] = e255;
            ssd[warp]  = q75 - q25 + 1e-6f;
        }
    }
    __syncthreads();
    if (tid < K_) {
        float sc = ssd[6] / ssd[tid];
        ssc[tid] = sc;
        ssh[tid] = smed[6] - smed[tid] * sc;
    }
    __syncthreads();

    // ---- map x_date in place; map+scale y_date ----
    #pragma unroll
    for (int k = 0; k < K_; k++) {
        const float sck = ssc[k], shk = ssh[k];
        for (int l = tid; l < L_; l += 256)
            sxd[k][l] = fmaf(sxd[k][l], sck, shk);
    }
    const float* yd_base = y_date + (size_t)b*O_*D_*K_ + (size_t)d*K_;
    for (int i = tid; i < O_*K_; i += 256) {
        int o = i / K_, k = i - o*K_;
        float v = yd_base[(size_t)o*(D_*K_) + k];
        syd[o][k] = fmaf(v, ssc[k], ssh[k]) * CSC;
    }
    __syncthreads();

    // ---- err = x - mean_k(map) ; ymean = mean_k(y_map) ----
    for (int l = tid; l < L_; l += 256) {
        float s = 0.f;
        #pragma unroll
        for (int k = 0; k < K_; k++) s += sxd[k][l];
        g_err[(size_t)bd*L_ + l] = sx[l] - s * (1.0f/6.0f);
    }
    for (int o = tid; o < O_; o += 256) {
        float s = syd[o][0]+syd[o][1]+syd[o][2]+syd[o][3]+syd[o][4]+syd[o][5];
        g_ymean[(size_t)bd*O_ + o] = s * INV6C;
    }

    // ---- single-pass softmax attention: 4 groups of 6 o's (3 f32x2 pairs) ----
    for (int og = 0; og < 4; og++) {
        const int o0 = warp*24 + og*6;
        ull y2[3][K_];
        #pragma unroll
        for (int p = 0; p < 3; p++)
            #pragma unroll
            for (int k = 0; k < K_; k++)
                PACK2(y2[p][k], syd[o0 + 2*p][k], syd[o0 + 2*p + 1][k]);

        ull sum2[3] = {0,0,0};
        ull vs2[3]  = {0,0,0};

        #pragma unroll
        for (int r = 0; r < 16; r++) {
            const int l = lane + (r << 5);
            ull xk[K_];
            #pragma unroll
            for (int k = 0; k < K_; k++) {
                float xs = sxd[k][l];
                PACK2(xk[k], xs, xs);
            }
            float xv = sx[l];
            ull xl2; PACK2(xl2, xv, xv);
            #pragma unroll
            for (int p = 0; p < 3; p++) {
                ull acc;
                MUL2(acc, xk[0], y2[p][0]);
                FMA2(acc, xk[1], y2[p][1], acc);
                FMA2(acc, xk[2], y2[p][2], acc);
                FMA2(acc, xk[3], y2[p][3], acc);
                FMA2(acc, xk[4], y2[p][4], acc);
                FMA2(acc, xk[5], y2[p][5], acc);
                float s0, s1; UNPACK2(s0, s1, acc);
                float p0, p1; EX2(p0, s0); EX2(p1, s1);
                ull pp; PACK2(pp, p0, p1);
                ADD2(sum2[p], sum2[p], pp);
                FMA2(vs2[p], pp, xl2, vs2[p]);
            }
        }
        #pragma unroll
        for (int p = 0; p < 3; p++) {
            #pragma unroll
            for (int off = 16; off; off >>= 1) {
                ull o1 = __shfl_xor_sync(0xffffffffu, sum2[p], off);
                ADD2(sum2[p], sum2[p], o1);
                ull o2 = __shfl_xor_sync(0xffffffffu, vs2[p], off);
                ADD2(vs2[p], vs2[p], o2);
            }
        }
        if (lane == 0) {
            #pragma unroll
            for (int p = 0; p < 3; p++) {
                float slo, shi, vlo, vhi;
                UNPACK2(slo, shi, sum2[p]);
                UNPACK2(vlo, vhi, vs2[p]);
                float va = vlo / slo, vb = vhi / shi;
                g_V[(size_t)bd*O_ + o0 + 2*p]     = va;
                g_V[(size_t)bd*O_ + o0 + 2*p + 1] = vb;
                sV[o0 + 2*p]     = va;
                sV[o0 + 2*p + 1] = vb;
            }
        }
    }
    __syncthreads();

    // ---- BN partials over this block's 192 o-values ----
    if (warp == 0) {
        float s = 0.f, sq = 0.f;
        for (int o = lane; o < O_; o += 32) {
            float v = sV[o];
            s += v;
            sq = fmaf(v, v, sq);
        }
        #pragma unroll
        for (int off = 16; off; off >>= 1) {
            s  += __shfl_xor_sync(0xffffffffu, s,  off);
            sq += __shfl_xor_sync(0xffffffffu, sq, off);
        }
        if (lane == 0) { g_psum[bd] = s; g_psq[bd] = sq; }
    }
}

// ---------------- kernel 2: f32x2 GEMM + gelu + fused gate-logit accumulation ----------------
__global__ void __launch_bounds__(256) mlp1_kernel(const float* __restrict__ w1,
                                                   const float* __restrict__ b1,
                                                   const float* __restrict__ w2) {
    __shared__ float Es[64][17];
    __shared__ __align__(16) float Ws[16][64];
    const int tx = threadIdx.x & 15, ty = threadIdx.x >> 4;
    const int row0 = blockIdx.y * 64, col0 = blockIdx.x * 64;
    ull acc2[4][2] = {};   // 4 rows x (2 f32x2 col-pairs) = 4x4 scalar tile

    for (int k0 = 0; k0 < 512; k0 += 16) {
        __syncthreads();
        #pragma unroll
        for (int it = 0; it < 4; it++) {
            int idx = threadIdx.x + it*256;
            int r  = idx >> 4, kk = idx & 15;
            Es[r][kk] = g_err[(size_t)(row0 + r)*512 + k0 + kk];
            int kw = idx >> 6, c = idx & 63;
            Ws[kw][c] = w1[(size_t)(k0 + kw)*512 + col0 + c];
        }
        __syncthreads();
        #pragma unroll
        for (int kk = 0; kk < 16; kk++) {
            const ull* wp = reinterpret_cast<const ull*>(&Ws[kk][tx*4]);
            const ull w0 = wp[0], w1v = wp[1];
            #pragma unroll
            for (int i = 0; i < 4; i++) {
                float a = Es[ty*4 + i][kk];
                ull ad; PACK2(ad, a, a);
                FMA2(acc2[i][0], ad, w0,  acc2[i][0]);
                FMA2(acc2[i][1], ad, w1v, acc2[i][1]);
            }
        }
    }
    #pragma unroll
    for (int i = 0; i < 4; i++) {
        const int row = row0 + ty*4 + i;
        float p0 = 0.f, p1 = 0.f;
        #pragma unroll
        for (int j = 0; j < 2; j++) {
            float c0, c1; UNPACK2(c0, c1, acc2[i][j]);
            #pragma unroll
            for (int h = 0; h < 2; h++) {
                const int col = col0 + tx*4 + 2*j + h;
                float v = (h ? c1 : c0) + b1[col];
                float g = 0.5f * v * (1.0f + erff(v * 0.7071067811865476f));
                p0 = fmaf(g, w2[col*2 + 0], p0);
                p1 = fmaf(g, w2[col*2 + 1], p1);
            }
        }
        #pragma unroll
        for (int off = 8; off; off >>= 1) {
            p0 += __shfl_xor_sync(0xffffffffu, p0, off);
            p1 += __shfl_xor_sync(0xffffffffu, p1, off);
        }
        if (tx == 0) {
            atomicAdd(&g_gl[row*2 + 0], p0);
            atomicAdd(&g_gl[row*2 + 1], p1);
        }
    }
}

// ---------------- kernel 3: BN final stats (1 block, 32 warps = 32 d's) ----------------
__global__ void bnfinal_kernel() {
    const int d = threadIdx.x >> 5, lane = threadIdx.x & 31;   // lane = b
    float s  = g_psum[lane*D_ + d];
    float sq = g_psq[lane*D_ + d];
    #pragma unroll
    for (int off = 16; off; off >>= 1) {
        s  += __shfl_xor_sync(0xffffffffu, s,  off);
        sq += __shfl_xor_sync(0xffffffffu, sq, off);
    }
    if (lane == 0) {
        float mu  = s * (1.0f / (B_*O_));
        float var = sq * (1.0f / (B_*O_)) - mu*mu;
        g_mu[d]   = mu;
        g_rstd[d] = rsqrtf(var + 1e-5f);
    }
}

// ---------------- kernel 4: coalesced BN apply + gate softmax + fusion ----------------
// grid (O_/32, B_); 256 threads. smem transpose: coalesced reads AND writes.
__global__ void __launch_bounds__(256) final_kernel(const float* __restrict__ bn_gamma,
                                                    const float* __restrict__ bn_beta,
                                                    const float* __restrict__ b2,
                                                    float* __restrict__ out) {
    __shared__ float tV[32][33], tY[32][33];
    const int b  = blockIdx.y;
    const int ot = blockIdx.x * 32;
    const int warp = threadIdx.x >> 5, lane = threadIdx.x & 31;

    #pragma unroll
    for (int i = 0; i < 4; i++) {
        const int d = warp*4 + i;
        const size_t base = ((size_t)(b*D_ + d))*O_ + ot + lane;
        tV[d][lane] = g_V[base];
        tY[d][lane] = g_ymean[base];
    }
    __syncthreads();

    // per-thread d = lane
    const int bd = b*D_ + lane;
    float l0 = g_gl[bd*2 + 0] + b2[0];
    float l1 = g_gl[bd*2 + 1] + b2[1];
    float m  = fmaxf(l0, l1);
    float e0 = __expf(l0 - m), e1 = __expf(l1 - m);
    float inv = 1.0f / (e0 + e1);
    const float w0 = e0 * inv, w1 = e1 * inv;
    const float mu = g_mu[lane], rstd = g_rstd[lane];
    const float ga = bn_gamma[lane], be = bn_beta[lane];

    #pragma unroll
    for (int i = 0; i < 4; i++) {
        const int oc = warp*4 + i;
        float v  = tV[lane][oc];
        float ym = tY[lane][oc];
        float y  = fmaf((v - mu) * rstd, ga, be);
        out[((size_t)(b*O_ + ot + oc))*D_ + lane] = ym * w0 + y * w1;
    }
}

// ---------------- launch ----------------
extern "C" void kernel_launch(void* const* d_in, const int* in_sizes, int n_in,
                              void* d_out, int out_size) {
    const float* x       = (const float*)d_in[0];
    const float* x_date  = (const float*)d_in[1];
    const float* y_date  = (const float*)d_in[2];
    const float* mlp_w1  = (const float*)d_in[3];
    const float* mlp_b1  = (const float*)d_in[4];
    const float* mlp_w2  = (const float*)d_in[5];
    const float* mlp_b2  = (const float*)d_in[6];
    const float* bn_gamma= (const float*)d_in[7];
    const float* bn_beta = (const float*)d_in[8];
    float* out = (float*)d_out;

    fused_kernel<<<B_*D_, 256>>>(x, x_date, y_date);
    bnfinal_kernel<<<1, 1024>>>();
    mlp1_kernel<<<dim3(DM_/64, (B_*D_)/64), 256>>>(mlp_w1, mlp_b1, mlp_w2);
    final_kernel<<<dim3(O_/32, B_), 256>>>(bn_gamma, bn_beta, mlp_b2, out);
}

// round 5
// speedup vs baseline: 1.7343x; 1.0117x over previous
#include <cuda_runtime.h>
#include <math.h>

#define B_  32
#define L_  512
#define D_  32
#define K_  6
#define O_  192
#define DM_ 512

typedef unsigned long long ull;

// ---------------- scratch (device globals) ----------------
__device__ float g_err[B_*D_*L_];      // (bd, l)
__device__ float g_ymean[B_*D_*O_];    // (bd, o)
__device__ float g_V[B_*D_*O_];        // (b,d,o)
__device__ float g_gl[B_*D_*2];        // gate logits (atomic-accumulated)
__device__ float g_psum[B_*D_];        // per-block BN partial sum
__device__ float g_psq[B_*D_];         // per-block BN partial sumsq

// ---------------- packed f32x2 helpers ----------------
#define MUL2(d,a,b)   asm("mul.rn.f32x2 %0, %1, %2;"      : "=l"(d) : "l"(a), "l"(b))
#define ADD2(d,a,b)   asm("add.rn.f32x2 %0, %1, %2;"      : "=l"(d) : "l"(a), "l"(b))
#define FMA2(d,a,b,c) asm("fma.rn.f32x2 %0, %1, %2, %3;"  : "=l"(d) : "l"(a), "l"(b), "l"(c))
#define PACK2(p,lo,hi)   asm("mov.b64 %0, {%1, %2};" : "=l"(p) : "f"(lo), "f"(hi))
#define UNPACK2(lo,hi,p) asm("mov.b64 {%0, %1}, %2;" : "=f"(lo), "=f"(hi) : "l"(p))
#define EX2(d,s)      asm("ex2.approx.f32 %0, %1;"        : "=f"(d) : "f"(s))

// ---------------- warp-register bitonic sort of 512 elems ----------------
__device__ __forceinline__ void warp_sort512(float v[16], int lane) {
    #pragma unroll
    for (int lsz = 1; lsz <= 9; lsz++) {
        const int size = 1 << lsz;
        #pragma unroll
        for (int s = size >> 1; s >= 16; s >>= 1) {
            const int plane = s >> 4;
            const bool up   = (lane & plane) == 0;
            const bool desc = (lane & (size >> 4)) != 0;
            const bool keepmin = (up != desc);
            #pragma unroll
            for (int i = 0; i < 16; i++) {
                float o = __shfl_xor_sync(0xffffffffu, v[i], plane);
                v[i] = keepmin ? fminf(v[i], o) : fmaxf(v[i], o);
            }
        }
        #pragma unroll
        for (int s = (size >= 32 ? 8 : size >> 1); s >= 1; s >>= 1) {
            #pragma unroll
            for (int i = 0; i < 16; i++) {
                if ((i & s) == 0) {
                    const bool desc = (size >= 16) ? ((lane & (size >> 4)) != 0)
                                                   : ((i & size) != 0);
                    float a = v[i], b = v[i | s];
                    float lo = fminf(a, b), hi = fmaxf(a, b);
                    v[i]     = desc ? hi : lo;
                    v[i | s] = desc ? lo : hi;
                }
            }
        }
    }
}

// ---------------- kernel 1: fused stats + map + attention + BN partials ----------------
// one block per (b,d); 256 threads = 8 warps; 2 blocks/SM (128-reg budget, no spills).
__global__ void __launch_bounds__(256, 2) fused_kernel(const float* __restrict__ x,
                                                       const float* __restrict__ x_date,
                                                       const float* __restrict__ y_date) {
    __shared__ float sxd[K_][L_];      // raw x_date, mapped IN PLACE (12 KB)
    __shared__ float sx[L_];           // x column (2 KB)
    __shared__ float syd[O_][K_];      // y_date, mapped in place * (1/sqrt6*log2e) (4.5 KB)
    __shared__ float sV[O_];           // V for BN partial
    __shared__ float smed[8], ssd[8];
    __shared__ float ssc[K_], ssh[K_];

    const int bd = blockIdx.x, tid = threadIdx.x;
    const int b = bd >> 5, d = bd & 31;
    const int warp = tid >> 5, lane = tid & 31;
    const float CSC = 0.408248290463863f * 1.4426950408889634f;  // 1/sqrt6 * log2e
    const float INV6C = (1.0f/6.0f) / CSC;

    // zero gate-logit accumulators (mlp1 runs strictly after this kernel)
    if (bd < 8) g_gl[bd*256 + tid] = 0.0f;

    // ---- stage ALL raw data into smem up front (y latency hides under sort) ----
    const float* xd_base = x_date + (size_t)b*L_*D_*K_ + (size_t)d*K_;
    for (int i = tid; i < L_*K_; i += 256) {
        int l = i / K_, k = i - l*K_;
        sxd[k][l] = xd_base[(size_t)l*(D_*K_) + k];
    }
    for (int l = tid; l < L_; l += 256)
        sx[l] = x[((size_t)b*L_ + l)*D_ + d];
    const float* yd_base = y_date + (size_t)b*O_*D_*K_ + (size_t)d*K_;
    for (int i = tid; i < O_*K_; i += 256) {
        int o = i / K_, k = i - o*K_;
        syd[o][k] = yd_base[(size_t)o*(D_*K_) + k];
    }
    __syncthreads();

    // ---- sort: warps 0..5 -> x_date[:,k], warp 6 -> x ----
    if (warp < 7) {
        float v[16];
        const float* src = (warp < 6) ? sxd[warp] : sx;
        #pragma unroll
        for (int i = 0; i < 16; i++) v[i] = src[lane + 32*i];
        warp_sort512(v, lane);
        const float e127 = __shfl_sync(0xffffffffu, v[15], 7);
        const float e128 = __shfl_sync(0xffffffffu, v[0],  8);
        const float e255 = __shfl_sync(0xffffffffu, v[15], 15);
        const float e383 = __shfl_sync(0xffffffffu, v[15], 23);
        const float e384 = __shfl_sync(0xffffffffu, v[0],  24);
        if (lane == 0) {
            const float q75 = e383 + 0.25f * (e384 - e383);
            const float q25 = e127 + 0.75f * (e128 - e127);
            smed[warp] = e255;
            ssd[warp]  = q75 - q25 + 1e-6f;
        }
    }
    __syncthreads();
    if (tid < K_) {
        float sc = ssd[6] / ssd[tid];
        ssc[tid] = sc;
        ssh[tid] = smed[6] - smed[tid] * sc;
    }
    __syncthreads();

    // ---- map x_date and y_date in place ----
    #pragma unroll
    for (int k = 0; k < K_; k++) {
        const float sck = ssc[k], shk = ssh[k];
        for (int l = tid; l < L_; l += 256)
            sxd[k][l] = fmaf(sxd[k][l], sck, shk);
    }
    for (int i = tid; i < O_*K_; i += 256) {
        int o = i / K_, k = i - o*K_;
        syd[o][k] = fmaf(syd[o][k], ssc[k], ssh[k]) * CSC;
    }
    __syncthreads();

    // ---- err = x - mean_k(map) ; ymean = mean_k(y_map) ----
    for (int l = tid; l < L_; l += 256) {
        float s = 0.f;
        #pragma unroll
        for (int k = 0; k < K_; k++) s += sxd[k][l];
        g_err[(size_t)bd*L_ + l] = sx[l] - s * (1.0f/6.0f);
    }
    for (int o = tid; o < O_; o += 256) {
        float s = syd[o][0]+syd[o][1]+syd[o][2]+syd[o][3]+syd[o][4]+syd[o][5];
        g_ymean[(size_t)bd*O_ + o] = s * INV6C;
    }

    // ---- single-pass softmax attention: l-pairs packed in f32x2, o dup-packed ----
    // warp owns o in [warp*24, warp*24+24), processed 4 at a time (6 groups).
    for (int og = 0; og < 6; og++) {
        const int o0 = warp*24 + og*4;
        ull y2[4][K_];
        #pragma unroll
        for (int p = 0; p < 4; p++)
            #pragma unroll
            for (int k = 0; k < K_; k++) {
                float yv = syd[o0 + p][k];
                PACK2(y2[p][k], yv, yv);
            }

        ull sum2[4] = {0,0,0,0};
        ull vs2[4]  = {0,0,0,0};

        #pragma unroll
        for (int pass = 0; pass < 8; pass++) {
            const int l = pass*64 + lane*2;
            ull xk2[K_];
            #pragma unroll
            for (int k = 0; k < K_; k++)
                xk2[k] = *reinterpret_cast<const ull*>(&sxd[k][l]);   // two adjacent l
            const ull x2 = *reinterpret_cast<const ull*>(&sx[l]);
            #pragma unroll
            for (int p = 0; p < 4; p++) {
                ull acc;
                MUL2(acc, xk2[0], y2[p][0]);
                FMA2(acc, xk2[1], y2[p][1], acc);
                FMA2(acc, xk2[2], y2[p][2], acc);
                FMA2(acc, xk2[3], y2[p][3], acc);
                FMA2(acc, xk2[4], y2[p][4], acc);
                FMA2(acc, xk2[5], y2[p][5], acc);
                float s0, s1; UNPACK2(s0, s1, acc);
                float e0, e1; EX2(e0, s0); EX2(e1, s1);
                ull pp; PACK2(pp, e0, e1);
                ADD2(sum2[p], sum2[p], pp);
                FMA2(vs2[p], pp, x2, vs2[p]);
            }
        }
        // combine halves -> scalar, then lane-reduce
        #pragma unroll
        for (int p = 0; p < 4; p++) {
            float slo, shi, vlo, vhi;
            UNPACK2(slo, shi, sum2[p]);
            UNPACK2(vlo, vhi, vs2[p]);
            float s = slo + shi, v = vlo + vhi;
            #pragma unroll
            for (int off = 16; off; off >>= 1) {
                s += __shfl_xor_sync(0xffffffffu, s, off);
                v += __shfl_xor_sync(0xffffffffu, v, off);
            }
            if (lane == 0) {
                float r = v / s;
                g_V[(size_t)bd*O_ + o0 + p] = r;
                sV[o0 + p] = r;
            }
        }
    }
    __syncthreads();

    // ---- BN partials over this block's 192 o-values ----
    if (warp == 0) {
        float s = 0.f, sq = 0.f;
        for (int o = lane; o < O_; o += 32) {
            float v = sV[o];
            s += v;
            sq = fmaf(v, v, sq);
        }
        #pragma unroll
        for (int off = 16; off; off >>= 1) {
            s  += __shfl_xor_sync(0xffffffffu, s,  off);
            sq += __shfl_xor_sync(0xffffffffu, sq, off);
        }
        if (lane == 0) { g_psum[bd] = s; g_psq[bd] = sq; }
    }
}

// ---------------- kernel 2: f32x2 GEMM + gelu + fused gate-logit accumulation ----------------
__global__ void __launch_bounds__(256) mlp1_kernel(const float* __restrict__ w1,
                                                   const float* __restrict__ b1,
                                                   const float* __restrict__ w2) {
    __shared__ float Es[64][17];
    __shared__ __align__(16) float Ws[16][64];
    const int tx = threadIdx.x & 15, ty = threadIdx.x >> 4;
    const int row0 = blockIdx.y * 64, col0 = blockIdx.x * 64;
    ull acc2[4][2] = {};

    for (int k0 = 0; k0 < 512; k0 += 16) {
        __syncthreads();
        #pragma unroll
        for (int it = 0; it < 4; it++) {
            int idx = threadIdx.x + it*256;
            int r  = idx >> 4, kk = idx & 15;
            Es[r][kk] = g_err[(size_t)(row0 + r)*512 + k0 + kk];
            int kw = idx >> 6, c = idx & 63;
            Ws[kw][c] = w1[(size_t)(k0 + kw)*512 + col0 + c];
        }
        __syncthreads();
        #pragma unroll
        for (int kk = 0; kk < 16; kk++) {
            const ull* wp = reinterpret_cast<const ull*>(&Ws[kk][tx*4]);
            const ull w0 = wp[0], w1v = wp[1];
            #pragma unroll
            for (int i = 0; i < 4; i++) {
                float a = Es[ty*4 + i][kk];
                ull ad; PACK2(ad, a, a);
                FMA2(acc2[i][0], ad, w0,  acc2[i][0]);
                FMA2(acc2[i][1], ad, w1v, acc2[i][1]);
            }
        }
    }
    #pragma unroll
    for (int i = 0; i < 4; i++) {
        const int row = row0 + ty*4 + i;
        float p0 = 0.f, p1 = 0.f;
        #pragma unroll
        for (int j = 0; j < 2; j++) {
            float c0, c1; UNPACK2(c0, c1, acc2[i][j]);
            #pragma unroll
            for (int h = 0; h < 2; h++) {
                const int col = col0 + tx*4 + 2*j + h;
                float v = (h ? c1 : c0) + b1[col];
                float g = 0.5f * v * (1.0f + erff(v * 0.7071067811865476f));
                p0 = fmaf(g, w2[col*2 + 0], p0);
                p1 = fmaf(g, w2[col*2 + 1], p1);
            }
        }
        #pragma unroll
        for (int off = 8; off; off >>= 1) {
            p0 += __shfl_xor_sync(0xffffffffu, p0, off);
            p1 += __shfl_xor_sync(0xffffffffu, p1, off);
        }
        if (tx == 0) {
            atomicAdd(&g_gl[row*2 + 0], p0);
            atomicAdd(&g_gl[row*2 + 1], p1);
        }
    }
}

// ---------------- kernel 3: BN reduce (redundant per block) + apply + gate + fusion ----------------
// grid (O_/32, B_); 256 threads. smem transpose: coalesced reads AND writes.
__global__ void __launch_bounds__(256) final_kernel(const float* __restrict__ bn_gamma,
                                                    const float* __restrict__ bn_beta,
                                                    const float* __restrict__ b2,
                                                    float* __restrict__ out) {
    __shared__ float tV[32][33], tY[32][33];
    __shared__ float rs[8][32], rq[8][32];
    __shared__ float smu[32], srstd[32];
    const int b  = blockIdx.y;
    const int ot = blockIdx.x * 32;
    const int warp = threadIdx.x >> 5, lane = threadIdx.x & 31;

    // redundant BN reduction over 1024 partials (coalesced: d = lane)
    {
        float s = 0.f, sq = 0.f;
        #pragma unroll
        for (int j = 0; j < 4; j++) {
            const int bb = warp + j*8;
            s  += g_psum[bb*D_ + lane];
            sq += g_psq[bb*D_ + lane];
        }
        rs[warp][lane] = s;
        rq[warp][lane] = sq;
    }

    #pragma unroll
    for (int i = 0; i < 4; i++) {
        const int d = warp*4 + i;
        const size_t base = ((size_t)(b*D_ + d))*O_ + ot + lane;
        tV[d][lane] = g_V[base];
        tY[d][lane] = g_ymean[base];
    }
    __syncthreads();

    if (threadIdx.x < 32) {
        float s = 0.f, sq = 0.f;
        #pragma unroll
        for (int w = 0; w < 8; w++) { s += rs[w][threadIdx.x]; sq += rq[w][threadIdx.x]; }
        float mu  = s * (1.0f / (B_*O_));
        float var = sq * (1.0f / (B_*O_)) - mu*mu;
        smu[threadIdx.x]   = mu;
        srstd[threadIdx.x] = rsqrtf(var + 1e-5f);
    }
    __syncthreads();

    // per-thread d = lane
    const int bd = b*D_ + lane;
    float l0 = g_gl[bd*2 + 0] + b2[0];
    float l1 = g_gl[bd*2 + 1] + b2[1];
    float m  = fmaxf(l0, l1);
    float e0 = __expf(l0 - m), e1 = __expf(l1 - m);
    float inv = 1.0f / (e0 + e1);
    const float w0 = e0 * inv, w1 = e1 * inv;
    const float mu = smu[lane], rstd = srstd[lane];
    const float ga = bn_gamma[lane], be = bn_beta[lane];

    #pragma unroll
    for (int i = 0; i < 4; i++) {
        const int oc = warp*4 + i;
        float v  = tV[lane][oc];
        float ym = tY[lane][oc];
        float y  = fmaf((v - mu) * rstd, ga, be);
        out[((size_t)(b*O_ + ot + oc))*D_ + lane] = ym * w0 + y * w1;
    }
}

// ---------------- launch ----------------
extern "C" void kernel_launch(void* const* d_in, const int* in_sizes, int n_in,
                              void* d_out, int out_size) {
    const float* x       = (const float*)d_in[0];
    const float* x_date  = (const float*)d_in[1];
    const float* y_date  = (const float*)d_in[2];
    const float* mlp_w1  = (const float*)d_in[3];
    const float* mlp_b1  = (const float*)d_in[4];
    const float* mlp_w2  = (const float*)d_in[5];
    const float* mlp_b2  = (const float*)d_in[6];
    const float* bn_gamma= (const float*)d_in[7];
    const float* bn_beta = (const float*)d_in[8];
    float* out = (float*)d_out;

    fused_kernel<<<B_*D_, 256>>>(x, x_date, y_date);
    mlp1_kernel<<<dim3(DM_/64, (B_*D_)/64), 256>>>(mlp_w1, mlp_b1, mlp_w2);
    final_kernel<<<dim3(O_/32, B_), 256>>>(bn_gamma, bn_beta, mlp_b2, out);
}